// round 5
// baseline (speedup 1.0000x reference)
#include <cuda_runtime.h>
#include <math.h>

#define Bq 2
#define Lq 1024
#define Aq 14
#define Kq 30
#define NRBF 16
#define NPEq 16
#define EFq 128
#define EDGEIN (NPEq + NRBF*Aq*Aq)   /* 3152 */
#define NKQ4 (EDGEIN/4)              /* 788 */
#define NE (Bq*Lq*Kq*EFq)
#define NK (Bq*Lq*Kq)
#define PADF 36                      /* floats per slot: 32 data + 4 pad (144B, 16B-aligned) */
#define NPACKBLK ((NKQ4*EFq + 255)/256)   /* 394 */

typedef unsigned long long ull;

__device__ int    g_Eidx[Bq*Lq*Kq];
__device__ float4 g_W4[NKQ4*EFq];    /* g_W4[kq*128+f] = {W[f][4kq..4kq+3]} */

// ---------------- packed f32x2 helpers ----------------
__device__ __forceinline__ ull fma2(ull a, ull b, ull c){
    ull d; asm("fma.rn.f32x2 %0,%1,%2,%3;" : "=l"(d) : "l"(a),"l"(b),"l"(c)); return d;
}
__device__ __forceinline__ ull rep2(float x){
    ull d; asm("mov.b64 %0,{%1,%1};" : "=l"(d) : "f"(x)); return d;
}
__device__ __forceinline__ ull pack2(float lo, float hi){
    ull d; asm("mov.b64 %0,{%1,%2};" : "=l"(d) : "f"(lo),"f"(hi)); return d;
}
__device__ __forceinline__ void unpack2(ull v, float& lo, float& hi){
    asm("mov.b64 {%0,%1},%2;" : "=f"(lo),"=f"(hi) : "l"(v));
}

// ---------------------------------------------------------------------------
// Prep kernel: blocks [0,NPACKBLK) pack W; blocks [NPACKBLK, +2048) do KNN.
// ---------------------------------------------------------------------------
__global__ void prep_kernel(const float* __restrict__ W,
                            const float* __restrict__ X,
                            const float* __restrict__ mask,
                            float* __restrict__ outIdxF) {
    __shared__ float sD[Lq];
    __shared__ float smax[8];
    __shared__ unsigned long long red[8];

    if (blockIdx.x < NPACKBLK) {
        int idx = blockIdx.x * 256 + threadIdx.x;
        if (idx < NKQ4 * EFq) {
            int kq = idx >> 7, f = idx & 127;
            const float* src = W + f * EDGEIN + kq * 4;
            g_W4[idx] = make_float4(src[0], src[1], src[2], src[3]);
        }
        return;
    }

    const int bi  = blockIdx.x - NPACKBLK;
    const int b   = bi / Lq;
    const int tid = threadIdx.x;

    const float mi  = mask[bi];
    const float xi0 = X[(bi*Aq + 1)*3 + 0];
    const float xi1 = X[(bi*Aq + 1)*3 + 1];
    const float xi2 = X[(bi*Aq + 1)*3 + 2];

    float lmax = 0.f;
    for (int j = tid; j < Lq; j += 256) {
        const float* xj = X + ((b*Lq + j)*Aq + 1)*3;
        float dx = xi0 - xj[0], dy = xi1 - xj[1], dz = xi2 - xj[2];
        float m2 = mi * mask[b*Lq + j];
        float D  = m2 * sqrtf(dx*dx + dy*dy + dz*dz + 1e-6f);
        sD[j] = D;
        lmax = fmaxf(lmax, D);
    }
    #pragma unroll
    for (int o = 16; o > 0; o >>= 1)
        lmax = fmaxf(lmax, __shfl_xor_sync(0xffffffffu, lmax, o));
    if ((tid & 31) == 0) smax[tid >> 5] = lmax;
    __syncthreads();
    float Dmax = smax[0];
    #pragma unroll
    for (int w = 1; w < 8; w++) Dmax = fmaxf(Dmax, smax[w]);

    for (int j = tid; j < Lq; j += 256) {
        float m2 = mi * mask[b*Lq + j];
        sD[j] += 2.f * (1.f - m2) * Dmax;
    }
    __syncthreads();

    for (int k = 0; k < Kq; k++) {
        unsigned long long best = 0xffffffffffffffffull;
        for (int j = tid; j < Lq; j += 256) {
            unsigned long long p =
                (((unsigned long long)__float_as_uint(sD[j])) << 32) | (unsigned)j;
            best = (p < best) ? p : best;
        }
        #pragma unroll
        for (int o = 16; o > 0; o >>= 1) {
            unsigned long long other = __shfl_xor_sync(0xffffffffu, best, o);
            best = (other < best) ? other : best;
        }
        if ((tid & 31) == 0) red[tid >> 5] = best;
        __syncthreads();
        if (tid == 0) {
            unsigned long long bb = red[0];
            #pragma unroll
            for (int w = 1; w < 8; w++) bb = (red[w] < bb) ? red[w] : bb;
            int j = (int)(bb & 0xffffffffull);
            g_Eidx[bi*Kq + k] = j;
            if (outIdxF) outIdxF[bi*Kq + k] = (float)j;
            sD[j] = __int_as_float(0x7f800000);
        }
        __syncthreads();
    }
}

// ---------------------------------------------------------------------------
__device__ __forceinline__ void loadX2(const float* __restrict__ Xres, int a, float* out3) {
    if (a == 4) {  // virtual Cb
        float Nx = Xres[0], Ny = Xres[1], Nz = Xres[2];
        float Cax= Xres[3], Cay= Xres[4], Caz= Xres[5];
        float Cx = Xres[6], Cy = Xres[7], Cz = Xres[8];
        float bx = Cax - Nx, by = Cay - Ny, bz = Caz - Nz;
        float cx = Cx - Cax, cy = Cy - Cay, cz = Cz - Caz;
        float ax = by*cz - bz*cy;
        float ay = bz*cx - bx*cz;
        float az = bx*cy - by*cx;
        out3[0] = -0.58273431f*ax + 0.56802827f*bx - 0.54067466f*cx + Cax;
        out3[1] = -0.58273431f*ay + 0.56802827f*by - 0.54067466f*cy + Cay;
        out3[2] = -0.58273431f*az + 0.56802827f*bz - 0.54067466f*cz + Caz;
    } else {
        out3[0] = Xres[a*3+0];
        out3[1] = Xres[a*3+1];
        out3[2] = Xres[a*3+2];
    }
}

// one k-group pass: 4 weights (broadcast-packed) x 15 e-pairs
__device__ __forceinline__ void pass4(float4 w, const float* __restrict__ FaBase,
                                      int qoff, ull* __restrict__ acc) {
    ull Wa = rep2(w.x), Wb = rep2(w.y), Wc = rep2(w.z), Wd = rep2(w.w);
    #pragma unroll
    for (int ep = 0; ep < 15; ep++) {
        const ulonglong2* m = (const ulonglong2*)(FaBase + ep*PADF);
        ulonglong2 qa = m[qoff], qb = m[qoff+1];
        ull A = fma2(qa.x, Wa, acc[ep]);
        A = fma2(qa.y, Wb, A);
        A = fma2(qb.x, Wc, A);
        A = fma2(qb.y, Wd, A);
        acc[ep] = A;
    }
}

// ---------------------------------------------------------------------------
// Fused edge kernel: flat active-chunk loop, W register double-buffering,
// half-slab F with conflict-free rotated production, FFMA2 consume.
// ---------------------------------------------------------------------------
__global__ __launch_bounds__(128) void edge_kernel(
    const float* __restrict__ X,
    const float* __restrict__ atom_mask,
    const float* __restrict__ gamma,
    const float* __restrict__ beta,
    float* __restrict__ outE) {

    const int bi = blockIdx.x;
    const int b  = bi / Lq, i = bi % Lq;
    const int tid = threadIdx.x;
    const int f = tid;

    __shared__ __align__(16) float FaU[3840];     // union: F half-slab / LN acc buffer
    __shared__ __align__(16) float Epos[Kq][NPEq];
    __shared__ float X2n[Kq][Aq][3];
    __shared__ float amn[Kq][Aq];
    __shared__ float X2i[Aq][3];
    __shared__ float ami[Aq];
    __shared__ int   jn[Kq];
    __shared__ float sg[EFq], sb[EFq];
    __shared__ int   alist[Aq];
    __shared__ int   nact;

    if (tid < Kq) jn[tid] = g_Eidx[bi*Kq + tid];
    if (tid < Aq) {
        loadX2(X + bi*Aq*3, tid, X2i[tid]);
        ami[tid] = 1.0f - atom_mask[bi*Aq + tid];
    }
    sg[tid] = gamma[tid];
    sb[tid] = beta[tid];
    __syncthreads();

    for (int t = tid; t < Kq*Aq; t += 128) {
        int e = t / Aq, a = t % Aq;
        int j = jn[e];
        loadX2(X + (b*Lq + j)*Aq*3, a, X2n[e][a]);
        amn[e][a] = 1.0f - atom_mask[(b*Lq + j)*Aq + a];
    }
    for (int t = tid; t < Kq*NPEq; t += 128) {
        int e = t / NPEq, p = t % NPEq;
        float d  = (float)jn[e] - (float)i;
        int   pp = p & 7;
        float fr = expf((float)(2*pp) * -0.57564627324851148f); // -ln(1e4)/16
        float ang = d * fr;
        Epos[e][p] = (p < 8) ? cosf(ang) : sinf(ang);
    }
    if (tid == 0) {
        int c = 0;
        #pragma unroll
        for (int a = 0; a < Aq; a++) if (ami[a] != 0.f) alist[c++] = a;
        nact = c;
    }
    __syncthreads();

    // ---- PE chunk: init acc (e-pair packed) ----
    ull acc[15];
    {
        float4 w0 = g_W4[0*EFq + f];
        float4 w1 = g_W4[1*EFq + f];
        float4 w2 = g_W4[2*EFq + f];
        float4 w3 = g_W4[3*EFq + f];
        #pragma unroll
        for (int ep = 0; ep < 15; ep++) {
            float pv[2];
            #pragma unroll
            for (int h = 0; h < 2; h++) {
                const float4* vp = (const float4*)Epos[2*ep + h];
                float4 a0 = vp[0], a1 = vp[1], a2 = vp[2], a3 = vp[3];
                float p0 = w0.x*a0.x; p0 = fmaf(w1.x, a1.x, p0); p0 = fmaf(w2.x, a2.x, p0); p0 = fmaf(w3.x, a3.x, p0);
                float p1 = w0.y*a0.y; p1 = fmaf(w1.y, a1.y, p1); p1 = fmaf(w2.y, a2.y, p1); p1 = fmaf(w3.y, a3.y, p1);
                float p2 = w0.z*a0.z; p2 = fmaf(w1.z, a1.z, p2); p2 = fmaf(w2.z, a2.z, p2); p2 = fmaf(w3.z, a3.z, p2);
                float p3 = w0.w*a0.w; p3 = fmaf(w1.w, a1.w, p3); p3 = fmaf(w2.w, a2.w, p3); p3 = fmaf(w3.w, a3.w, p3);
                pv[h] = (p0 + p1) + (p2 + p3);
            }
            acc[ep] = pack2(pv[0], pv[1]);
        }
    }

    // ---- main flat chunk loop ----
    const int nchunks = nact * Aq;
    float4 wc0, wc1, wc2, wc3;
    if (nchunks > 0) {
        int a0 = alist[0];
        int kq0 = 4 + (a0*Aq + 0)*4;
        wc0 = g_W4[(kq0+0)*EFq + f];
        wc1 = g_W4[(kq0+1)*EFq + f];
        wc2 = g_W4[(kq0+2)*EFq + f];
        wc3 = g_W4[(kq0+3)*EFq + f];
    }

    for (int ci = 0; ci < nchunks; ci++) {
        const int a  = alist[ci / Aq];
        const int b2 = ci - (ci / Aq) * Aq;

        if (b2 == 0 || b2 == 7) {
            __syncthreads();          // previous consume of FaU finished
            if (tid < 105) {
                const int ep  = tid / 7;
                const int b2l = tid % 7;
                const int b2g = ((b2 >= 7) ? 7 : 0) + b2l;
                const float xa0 = X2i[a][0], xa1 = X2i[a][1], xa2 = X2i[a][2];
                const int e0 = 2*ep, e1 = e0 + 1;
                const float act0 = amn[e0][b2g];
                const float act1 = amn[e1][b2g];
                float dx = xa0 - X2n[e0][b2g][0];
                float dy = xa1 - X2n[e0][b2g][1];
                float dz = xa2 - X2n[e0][b2g][2];
                const float D0 = sqrtf(dx*dx + dy*dy + dz*dz + 1e-6f);
                dx = xa0 - X2n[e1][b2g][0];
                dy = xa1 - X2n[e1][b2g][1];
                dz = xa2 - X2n[e1][b2g][2];
                const float D1 = sqrtf(dx*dx + dy*dy + dz*dz + 1e-6f);
                float* slot = &FaU[(b2l*15 + ep)*PADF];
                #pragma unroll
                for (int rr = 0; rr < NRBF; rr++) {
                    const int r = (rr + tid) & 15;       // bank-conflict rotation
                    const float mu = (float)r * (20.f/15.f);
                    float x0 = (D0 - mu) * 0.8f;
                    float x1 = (D1 - mu) * 0.8f;
                    float v0 = __expf(-x0*x0) * act0;
                    float v1 = __expf(-x1*x1) * act1;
                    *(float2*)(slot + 2*r) = make_float2(v0, v1);
                }
            }
            __syncthreads();
        }

        // prefetch next chunk's weights (hidden under consume)
        float4 wn0 = wc0, wn1 = wc1, wn2 = wc2, wn3 = wc3;
        const int cn = ci + 1;
        if (cn < nchunks) {
            const int an  = alist[cn / Aq];
            const int b2n = cn - (cn / Aq) * Aq;
            const int kqn = 4 + (an*Aq + b2n)*4;
            wn0 = g_W4[(kqn+0)*EFq + f];
            wn1 = g_W4[(kqn+1)*EFq + f];
            wn2 = g_W4[(kqn+2)*EFq + f];
            wn3 = g_W4[(kqn+3)*EFq + f];
        }

        // consume (branch-free, dense e, packed FFMA2, 4 k-group passes)
        const int b2l = (b2 >= 7) ? (b2 - 7) : b2;
        const float* FaBase = &FaU[b2l * 15 * PADF];
        pass4(wc0, FaBase, 0, acc);
        pass4(wc1, FaBase, 2, acc);
        pass4(wc2, FaBase, 4, acc);
        pass4(wc3, FaBase, 6, acc);

        wc0 = wn0; wc1 = wn1; wc2 = wn2; wc3 = wn3;
    }

    // ---- dump acc pairs to smem (reusing FaU), then LayerNorm ----
    __syncthreads();
    #pragma unroll
    for (int ep = 0; ep < 15; ep++) {
        float lo, hi; unpack2(acc[ep], lo, hi);
        *(float2*)&FaU[(ep*EFq + f)*2] = make_float2(lo, hi);
    }
    __syncthreads();

    const int wid = tid >> 5, lid = tid & 31;
    float* outRow = outE + (size_t)bi * (Kq*EFq);
    for (int e = wid; e < Kq; e += 4) {
        const int ep = e >> 1, par = e & 1;
        const float* ab = &FaU[ep*EFq*2 + par];
        float v0 = ab[(lid      )*2];
        float v1 = ab[(lid + 32 )*2];
        float v2 = ab[(lid + 64 )*2];
        float v3 = ab[(lid + 96 )*2];
        float s  = (v0 + v1) + (v2 + v3);
        float sq = fmaf(v0,v0, fmaf(v1,v1, fmaf(v2,v2, v3*v3)));
        #pragma unroll
        for (int o = 16; o > 0; o >>= 1) {
            s  += __shfl_xor_sync(0xffffffffu, s,  o);
            sq += __shfl_xor_sync(0xffffffffu, sq, o);
        }
        float mean = s * (1.f/EFq);
        float var  = sq * (1.f/EFq) - mean*mean;
        float rstd = rsqrtf(var + 1e-5f);
        float* o0 = outRow + e*EFq;
        o0[lid     ] = (v0 - mean) * rstd * sg[lid     ] + sb[lid     ];
        o0[lid + 32] = (v1 - mean) * rstd * sg[lid + 32] + sb[lid + 32];
        o0[lid + 64] = (v2 - mean) * rstd * sg[lid + 64] + sb[lid + 64];
        o0[lid + 96] = (v3 - mean) * rstd * sg[lid + 96] + sb[lid + 96];
    }
}

// ---------------------------------------------------------------------------
extern "C" void kernel_launch(void* const* d_in, const int* in_sizes, int n_in,
                              void* d_out, int out_size) {
    const float* X         = (const float*)d_in[0];
    const float* mask      = (const float*)d_in[1];
    const float* atom_mask = (const float*)d_in[4];
    const float* W         = (const float*)d_in[5];
    const float* gamma     = (const float*)d_in[6];
    const float* beta      = (const float*)d_in[7];

    float* outE   = (float*)d_out;
    float* outIdx = (out_size >= NE + NK) ? (outE + NE) : nullptr;

    prep_kernel<<<NPACKBLK + Bq*Lq, 256>>>(W, X, mask, outIdx);
    edge_kernel<<<Bq*Lq, 128>>>(X, atom_mask, gamma, beta, outE);
}

// round 9
// speedup vs baseline: 1.3157x; 1.3157x over previous
#include <cuda_runtime.h>
#include <math.h>

#define Bq 2
#define Lq 1024
#define Aq 14
#define Kq 30
#define NRBF 16
#define NPEq 16
#define EFq 128
#define EDGEIN (NPEq + NRBF*Aq*Aq)   /* 3152 */
#define NKQ4 (EDGEIN/4)              /* 788 */
#define NE (Bq*Lq*Kq*EFq)
#define NK (Bq*Lq*Kq)
#define PADF 36                      /* floats per slot: 32 data + 4 pad (144B) */
#define NPACKBLK ((NKQ4*EFq + 255)/256)   /* 394 */

typedef unsigned long long ull;

__device__ int    g_Eidx[Bq*Lq*Kq];
__device__ float4 g_W4[NKQ4*EFq];    /* g_W4[kq*128+f] = {W[f][4kq..4kq+3]} */

// ---------------- packed f32x2 helpers ----------------
__device__ __forceinline__ ull fma2(ull a, ull b, ull c){
    ull d; asm("fma.rn.f32x2 %0,%1,%2,%3;" : "=l"(d) : "l"(a),"l"(b),"l"(c)); return d;
}
__device__ __forceinline__ ull rep2(float x){
    ull d; asm("mov.b64 %0,{%1,%1};" : "=l"(d) : "f"(x)); return d;
}
__device__ __forceinline__ ull pack2(float lo, float hi){
    ull d; asm("mov.b64 %0,{%1,%2};" : "=l"(d) : "f"(lo),"f"(hi)); return d;
}
__device__ __forceinline__ void unpack2(ull v, float& lo, float& hi){
    asm("mov.b64 {%0,%1},%2;" : "=f"(lo),"=f"(hi) : "l"(v));
}

// ---------------------------------------------------------------------------
// Prep kernel: blocks [0,NPACKBLK) pack W; blocks [NPACKBLK, +2048) do KNN.
// ---------------------------------------------------------------------------
__global__ void prep_kernel(const float* __restrict__ W,
                            const float* __restrict__ X,
                            const float* __restrict__ mask,
                            float* __restrict__ outIdxF) {
    __shared__ float sD[Lq];
    __shared__ float smax[8];
    __shared__ unsigned long long red[8];

    if (blockIdx.x < NPACKBLK) {
        int idx = blockIdx.x * 256 + threadIdx.x;
        if (idx < NKQ4 * EFq) {
            int kq = idx >> 7, f = idx & 127;
            const float* src = W + f * EDGEIN + kq * 4;
            g_W4[idx] = make_float4(src[0], src[1], src[2], src[3]);
        }
        return;
    }

    const int bi  = blockIdx.x - NPACKBLK;
    const int b   = bi / Lq;
    const int tid = threadIdx.x;

    const float mi  = mask[bi];
    const float xi0 = X[(bi*Aq + 1)*3 + 0];
    const float xi1 = X[(bi*Aq + 1)*3 + 1];
    const float xi2 = X[(bi*Aq + 1)*3 + 2];

    float lmax = 0.f;
    for (int j = tid; j < Lq; j += 256) {
        const float* xj = X + ((b*Lq + j)*Aq + 1)*3;
        float dx = xi0 - xj[0], dy = xi1 - xj[1], dz = xi2 - xj[2];
        float m2 = mi * mask[b*Lq + j];
        float D  = m2 * sqrtf(dx*dx + dy*dy + dz*dz + 1e-6f);
        sD[j] = D;
        lmax = fmaxf(lmax, D);
    }
    #pragma unroll
    for (int o = 16; o > 0; o >>= 1)
        lmax = fmaxf(lmax, __shfl_xor_sync(0xffffffffu, lmax, o));
    if ((tid & 31) == 0) smax[tid >> 5] = lmax;
    __syncthreads();
    float Dmax = smax[0];
    #pragma unroll
    for (int w = 1; w < 8; w++) Dmax = fmaxf(Dmax, smax[w]);

    for (int j = tid; j < Lq; j += 256) {
        float m2 = mi * mask[b*Lq + j];
        sD[j] += 2.f * (1.f - m2) * Dmax;
    }
    __syncthreads();

    for (int k = 0; k < Kq; k++) {
        unsigned long long best = 0xffffffffffffffffull;
        for (int j = tid; j < Lq; j += 256) {
            unsigned long long p =
                (((unsigned long long)__float_as_uint(sD[j])) << 32) | (unsigned)j;
            best = (p < best) ? p : best;
        }
        #pragma unroll
        for (int o = 16; o > 0; o >>= 1) {
            unsigned long long other = __shfl_xor_sync(0xffffffffu, best, o);
            best = (other < best) ? other : best;
        }
        if ((tid & 31) == 0) red[tid >> 5] = best;
        __syncthreads();
        if (tid == 0) {
            unsigned long long bb = red[0];
            #pragma unroll
            for (int w = 1; w < 8; w++) bb = (red[w] < bb) ? red[w] : bb;
            int j = (int)(bb & 0xffffffffull);
            g_Eidx[bi*Kq + k] = j;
            if (outIdxF) outIdxF[bi*Kq + k] = (float)j;
            sD[j] = __int_as_float(0x7f800000);
        }
        __syncthreads();
    }
}

// ---------------------------------------------------------------------------
__device__ __forceinline__ void loadX2(const float* __restrict__ Xres, int a, float* out3) {
    if (a == 4) {  // virtual Cb
        float Nx = Xres[0], Ny = Xres[1], Nz = Xres[2];
        float Cax= Xres[3], Cay= Xres[4], Caz= Xres[5];
        float Cx = Xres[6], Cy = Xres[7], Cz = Xres[8];
        float bx = Cax - Nx, by = Cay - Ny, bz = Caz - Nz;
        float cx = Cx - Cax, cy = Cy - Cay, cz = Cz - Caz;
        float ax = by*cz - bz*cy;
        float ay = bz*cx - bx*cz;
        float az = bx*cy - by*cx;
        out3[0] = -0.58273431f*ax + 0.56802827f*bx - 0.54067466f*cx + Cax;
        out3[1] = -0.58273431f*ay + 0.56802827f*by - 0.54067466f*cy + Cay;
        out3[2] = -0.58273431f*az + 0.56802827f*bz - 0.54067466f*cz + Caz;
    } else {
        out3[0] = Xres[a*3+0];
        out3[1] = Xres[a*3+1];
        out3[2] = Xres[a*3+2];
    }
}

// ---------------------------------------------------------------------------
// Consume one chunk for this thread's e-pair range [EP0, EP0+NEP) and its
// two features. Each LDS.128 (2 e-paired r values) feeds 8 fma2.
// ---------------------------------------------------------------------------
template<int EP0, int NEP>
__device__ __forceinline__ void consume_chunk(
    const float* __restrict__ FaBase,
    const float* __restrict__ wf0,   // 16 weights for f0
    const float* __restrict__ wf1,   // 16 weights for f1
    ull* __restrict__ acc0, ull* __restrict__ acc1)
{
    #pragma unroll
    for (int p = 0; p < 4; p++) {
        ull A0 = rep2(wf0[4*p+0]), A1 = rep2(wf0[4*p+1]);
        ull A2 = rep2(wf0[4*p+2]), A3 = rep2(wf0[4*p+3]);
        ull B0 = rep2(wf1[4*p+0]), B1 = rep2(wf1[4*p+1]);
        ull B2 = rep2(wf1[4*p+2]), B3 = rep2(wf1[4*p+3]);
        #pragma unroll
        for (int ei = 0; ei < NEP; ei++) {
            const ulonglong2* m =
                (const ulonglong2*)(FaBase + (EP0+ei)*PADF) + 2*p;
            ulonglong2 qa = m[0], qb = m[1];
            ull a0 = fma2(qa.x, A0, acc0[ei]);
            ull a1 = fma2(qa.x, B0, acc1[ei]);
            a0 = fma2(qa.y, A1, a0);
            a1 = fma2(qa.y, B1, a1);
            a0 = fma2(qb.x, A2, a0);
            a1 = fma2(qb.x, B2, a1);
            a0 = fma2(qb.y, A3, a0);
            a1 = fma2(qb.y, B3, a1);
            acc0[ei] = a0;
            acc1[ei] = a1;
        }
    }
}

// ---------------------------------------------------------------------------
// Fused edge kernel: 2 features/thread, e-pairs split across warp groups.
// Block = one (b,i) residue, 128 threads.
//   warps 0-1 (tid 0..63):   e-pairs 0..6,  features f=tid, tid+64
//   warps 2-3 (tid 64..127): e-pairs 7..14, features f=tid-64, tid
// ---------------------------------------------------------------------------
__global__ __launch_bounds__(128) void edge_kernel(
    const float* __restrict__ X,
    const float* __restrict__ atom_mask,
    const float* __restrict__ gamma,
    const float* __restrict__ beta,
    float* __restrict__ outE) {

    const int bi = blockIdx.x;
    const int b  = bi / Lq, i = bi % Lq;
    const int tid = threadIdx.x;

    const int grp   = (tid >= 64);
    const int lt    = tid & 63;
    const int f0    = lt;
    const int f1    = lt + 64;
    const int myEP0 = grp ? 7 : 0;
    const int myNEP = grp ? 8 : 7;

    __shared__ __align__(16) float FaU[3840];     // F half-slab / LN acc buffer
    __shared__ __align__(16) float Epos[Kq][NPEq];
    __shared__ float X2n[Kq][Aq][3];
    __shared__ float amn[Kq][Aq];
    __shared__ float X2i[Aq][3];
    __shared__ float ami[Aq];
    __shared__ int   jn[Kq];
    __shared__ float sg[EFq], sb[EFq];
    __shared__ int   alist[Aq];
    __shared__ int   nact;

    if (tid < Kq) jn[tid] = g_Eidx[bi*Kq + tid];
    if (tid < Aq) {
        loadX2(X + bi*Aq*3, tid, X2i[tid]);
        ami[tid] = 1.0f - atom_mask[bi*Aq + tid];
    }
    sg[tid] = gamma[tid];
    sb[tid] = beta[tid];
    __syncthreads();

    for (int t = tid; t < Kq*Aq; t += 128) {
        int e = t / Aq, a = t % Aq;
        int j = jn[e];
        loadX2(X + (b*Lq + j)*Aq*3, a, X2n[e][a]);
        amn[e][a] = 1.0f - atom_mask[(b*Lq + j)*Aq + a];
    }
    for (int t = tid; t < Kq*NPEq; t += 128) {
        int e = t / NPEq, p = t % NPEq;
        float d  = (float)jn[e] - (float)i;
        int   pp = p & 7;
        float fr = expf((float)(2*pp) * -0.57564627324851148f); // -ln(1e4)/16
        float ang = d * fr;
        Epos[e][p] = (p < 8) ? cosf(ang) : sinf(ang);
    }
    if (tid == 0) {
        int c = 0;
        #pragma unroll
        for (int a = 0; a < Aq; a++) if (ami[a] != 0.f) alist[c++] = a;
        nact = c;
    }
    __syncthreads();

    // ---- PE chunk: init acc for my eps & 2 features (one-time) ----
    ull acc0[8], acc1[8];
    {
        float w0[16], w1[16];
        #pragma unroll
        for (int kq = 0; kq < 4; kq++) {
            float4 v0 = g_W4[kq*EFq + f0];
            float4 v1 = g_W4[kq*EFq + f1];
            w0[4*kq+0]=v0.x; w0[4*kq+1]=v0.y; w0[4*kq+2]=v0.z; w0[4*kq+3]=v0.w;
            w1[4*kq+0]=v1.x; w1[4*kq+1]=v1.y; w1[4*kq+2]=v1.z; w1[4*kq+3]=v1.w;
        }
        #pragma unroll
        for (int ei = 0; ei < 8; ei++) {
            acc0[ei] = 0; acc1[ei] = 0;
            if (ei < myNEP) {
                float pv0[2], pv1[2];
                #pragma unroll
                for (int h = 0; h < 2; h++) {
                    const float* vp = Epos[2*(myEP0+ei) + h];
                    float s0 = 0.f, s1 = 0.f;
                    #pragma unroll
                    for (int k = 0; k < 16; k++) {
                        float v = vp[k];
                        s0 = fmaf(w0[k], v, s0);
                        s1 = fmaf(w1[k], v, s1);
                    }
                    pv0[h] = s0; pv1[h] = s1;
                }
                acc0[ei] = pack2(pv0[0], pv0[1]);
                acc1[ei] = pack2(pv1[0], pv1[1]);
            }
        }
    }

    // ---- main flat chunk loop ----
    const int nchunks = nact * Aq;
    for (int ci = 0; ci < nchunks; ci++) {
        const int ai = ci / Aq;
        const int a  = alist[ai];
        const int b2 = ci - ai * Aq;

        if (b2 == 0 || b2 == 7) {
            __syncthreads();          // previous consume of FaU finished
            if (tid < 105) {
                const int ep  = tid / 7;
                const int b2l = tid % 7;
                const int b2g = ((b2 >= 7) ? 7 : 0) + b2l;
                const float xa0 = X2i[a][0], xa1 = X2i[a][1], xa2 = X2i[a][2];
                const int e0 = 2*ep, e1 = e0 + 1;
                const float act0 = amn[e0][b2g];
                const float act1 = amn[e1][b2g];
                float dx = xa0 - X2n[e0][b2g][0];
                float dy = xa1 - X2n[e0][b2g][1];
                float dz = xa2 - X2n[e0][b2g][2];
                const float D0 = sqrtf(dx*dx + dy*dy + dz*dz + 1e-6f);
                dx = xa0 - X2n[e1][b2g][0];
                dy = xa1 - X2n[e1][b2g][1];
                dz = xa2 - X2n[e1][b2g][2];
                const float D1 = sqrtf(dx*dx + dy*dy + dz*dz + 1e-6f);
                float* slot = &FaU[(b2l*15 + ep)*PADF];
                #pragma unroll
                for (int rr = 0; rr < NRBF; rr++) {
                    const int r = (rr + tid) & 15;       // bank rotation
                    const float mu = (float)r * (20.f/15.f);
                    float x0 = (D0 - mu) * 0.8f;
                    float x1 = (D1 - mu) * 0.8f;
                    float v0 = __expf(-x0*x0) * act0;
                    float v1 = __expf(-x1*x1) * act1;
                    *(float2*)(slot + 2*r) = make_float2(v0, v1);
                }
            }
            __syncthreads();
        }

        // load this chunk's 16 weights for my 2 features (coalesced, L1-hot)
        float w0[16], w1[16];
        const int kq0 = 4 + (a*Aq + b2)*4;
        #pragma unroll
        for (int kq = 0; kq < 4; kq++) {
            float4 v0 = g_W4[(kq0+kq)*EFq + f0];
            float4 v1 = g_W4[(kq0+kq)*EFq + f1];
            w0[4*kq+0]=v0.x; w0[4*kq+1]=v0.y; w0[4*kq+2]=v0.z; w0[4*kq+3]=v0.w;
            w1[4*kq+0]=v1.x; w1[4*kq+1]=v1.y; w1[4*kq+2]=v1.z; w1[4*kq+3]=v1.w;
        }

        const int b2l = (b2 >= 7) ? (b2 - 7) : b2;
        const float* FaBase = &FaU[b2l * 15 * PADF];
        if (grp == 0) consume_chunk<0,7>(FaBase, w0, w1, acc0, acc1);
        else          consume_chunk<7,8>(FaBase, w0, w1, acc0, acc1);
    }

    // ---- dump acc pairs to smem (reusing FaU), then LayerNorm ----
    __syncthreads();
    #pragma unroll
    for (int ei = 0; ei < 8; ei++) {
        if (ei < myNEP) {
            const int ep = myEP0 + ei;
            float lo, hi;
            unpack2(acc0[ei], lo, hi);
            *(float2*)&FaU[(ep*EFq + f0)*2] = make_float2(lo, hi);
            unpack2(acc1[ei], lo, hi);
            *(float2*)&FaU[(ep*EFq + f1)*2] = make_float2(lo, hi);
        }
    }
    __syncthreads();

    const int wid = tid >> 5, lid = tid & 31;
    float* outRow = outE + (size_t)bi * (Kq*EFq);
    for (int e = wid; e < Kq; e += 4) {
        const int ep = e >> 1, par = e & 1;
        const float* ab = &FaU[ep*EFq*2 + par];
        float v0 = ab[(lid      )*2];
        float v1 = ab[(lid + 32 )*2];
        float v2 = ab[(lid + 64 )*2];
        float v3 = ab[(lid + 96 )*2];
        float s  = (v0 + v1) + (v2 + v3);
        float sq = fmaf(v0,v0, fmaf(v1,v1, fmaf(v2,v2, v3*v3)));
        #pragma unroll
        for (int o = 16; o > 0; o >>= 1) {
            s  += __shfl_xor_sync(0xffffffffu, s,  o);
            sq += __shfl_xor_sync(0xffffffffu, sq, o);
        }
        float mean = s * (1.f/EFq);
        float var  = sq * (1.f/EFq) - mean*mean;
        float rstd = rsqrtf(var + 1e-5f);
        float* o0 = outRow + e*EFq;
        o0[lid     ] = (v0 - mean) * rstd * sg[lid     ] + sb[lid     ];
        o0[lid + 32] = (v1 - mean) * rstd * sg[lid + 32] + sb[lid + 32];
        o0[lid + 64] = (v2 - mean) * rstd * sg[lid + 64] + sb[lid + 64];
        o0[lid + 96] = (v3 - mean) * rstd * sg[lid + 96] + sb[lid + 96];
    }
}

// ---------------------------------------------------------------------------
extern "C" void kernel_launch(void* const* d_in, const int* in_sizes, int n_in,
                              void* d_out, int out_size) {
    const float* X         = (const float*)d_in[0];
    const float* mask      = (const float*)d_in[1];
    const float* atom_mask = (const float*)d_in[4];
    const float* W         = (const float*)d_in[5];
    const float* gamma     = (const float*)d_in[6];
    const float* beta      = (const float*)d_in[7];

    float* outE   = (float*)d_out;
    float* outIdx = (out_size >= NE + NK) ? (outE + NE) : nullptr;

    prep_kernel<<<NPACKBLK + Bq*Lq, 256>>>(W, X, mask, outIdx);
    edge_kernel<<<Bq*Lq, 128>>>(X, atom_mask, gamma, beta, outE);
}

// round 11
// speedup vs baseline: 1.3453x; 1.0225x over previous
#include <cuda_runtime.h>
#include <math.h>

#define Bq 2
#define Lq 1024
#define Aq 14
#define Kq 30
#define NRBF 16
#define NPEq 16
#define EFq 128
#define EDGEIN (NPEq + NRBF*Aq*Aq)   /* 3152 */
#define NKQ4 (EDGEIN/4)              /* 788 */
#define NE (Bq*Lq*Kq*EFq)
#define NK (Bq*Lq*Kq)
#define PADF 36                      /* floats per slot: 32 data + 4 pad (144B) */
#define NPACKBLK ((NKQ4*EFq + 255)/256)   /* 394 */

typedef unsigned long long ull;

__device__ int    g_Eidx[Bq*Lq*Kq];
__device__ float4 g_W4[NKQ4*EFq];    /* g_W4[kq*128+f] = {W[f][4kq..4kq+3]} */

// ---------------- packed f32x2 helpers ----------------
__device__ __forceinline__ ull fma2(ull a, ull b, ull c){
    ull d; asm("fma.rn.f32x2 %0,%1,%2,%3;" : "=l"(d) : "l"(a),"l"(b),"l"(c)); return d;
}
__device__ __forceinline__ ull rep2(float x){
    ull d; asm("mov.b64 %0,{%1,%1};" : "=l"(d) : "f"(x)); return d;
}
__device__ __forceinline__ ull pack2(float lo, float hi){
    ull d; asm("mov.b64 %0,{%1,%2};" : "=l"(d) : "f"(lo),"f"(hi)); return d;
}
__device__ __forceinline__ void unpack2(ull v, float& lo, float& hi){
    asm("mov.b64 {%0,%1},%2;" : "=f"(lo),"=f"(hi) : "l"(v));
}

// ---------------------------------------------------------------------------
// Prep kernel: blocks [0,NPACKBLK) pack W; blocks [NPACKBLK, +2048) do KNN.
// ---------------------------------------------------------------------------
__global__ void prep_kernel(const float* __restrict__ W,
                            const float* __restrict__ X,
                            const float* __restrict__ mask,
                            float* __restrict__ outIdxF) {
    __shared__ float sD[Lq];
    __shared__ float smax[8];
    __shared__ unsigned long long red[8];

    if (blockIdx.x < NPACKBLK) {
        int idx = blockIdx.x * 256 + threadIdx.x;
        if (idx < NKQ4 * EFq) {
            int kq = idx >> 7, f = idx & 127;
            const float* src = W + f * EDGEIN + kq * 4;
            g_W4[idx] = make_float4(src[0], src[1], src[2], src[3]);
        }
        return;
    }

    const int bi  = blockIdx.x - NPACKBLK;
    const int b   = bi / Lq;
    const int tid = threadIdx.x;

    const float mi  = mask[bi];
    const float xi0 = X[(bi*Aq + 1)*3 + 0];
    const float xi1 = X[(bi*Aq + 1)*3 + 1];
    const float xi2 = X[(bi*Aq + 1)*3 + 2];

    float lmax = 0.f;
    for (int j = tid; j < Lq; j += 256) {
        const float* xj = X + ((b*Lq + j)*Aq + 1)*3;
        float dx = xi0 - xj[0], dy = xi1 - xj[1], dz = xi2 - xj[2];
        float m2 = mi * mask[b*Lq + j];
        float D  = m2 * sqrtf(dx*dx + dy*dy + dz*dz + 1e-6f);
        sD[j] = D;
        lmax = fmaxf(lmax, D);
    }
    #pragma unroll
    for (int o = 16; o > 0; o >>= 1)
        lmax = fmaxf(lmax, __shfl_xor_sync(0xffffffffu, lmax, o));
    if ((tid & 31) == 0) smax[tid >> 5] = lmax;
    __syncthreads();
    float Dmax = smax[0];
    #pragma unroll
    for (int w = 1; w < 8; w++) Dmax = fmaxf(Dmax, smax[w]);

    for (int j = tid; j < Lq; j += 256) {
        float m2 = mi * mask[b*Lq + j];
        sD[j] += 2.f * (1.f - m2) * Dmax;
    }
    __syncthreads();

    for (int k = 0; k < Kq; k++) {
        unsigned long long best = 0xffffffffffffffffull;
        for (int j = tid; j < Lq; j += 256) {
            unsigned long long p =
                (((unsigned long long)__float_as_uint(sD[j])) << 32) | (unsigned)j;
            best = (p < best) ? p : best;
        }
        #pragma unroll
        for (int o = 16; o > 0; o >>= 1) {
            unsigned long long other = __shfl_xor_sync(0xffffffffu, best, o);
            best = (other < best) ? other : best;
        }
        if ((tid & 31) == 0) red[tid >> 5] = best;
        __syncthreads();
        if (tid == 0) {
            unsigned long long bb = red[0];
            #pragma unroll
            for (int w = 1; w < 8; w++) bb = (red[w] < bb) ? red[w] : bb;
            int j = (int)(bb & 0xffffffffull);
            g_Eidx[bi*Kq + k] = j;
            if (outIdxF) outIdxF[bi*Kq + k] = (float)j;
            sD[j] = __int_as_float(0x7f800000);
        }
        __syncthreads();
    }
}

// ---------------------------------------------------------------------------
__device__ __forceinline__ void loadX2(const float* __restrict__ Xres, int a, float* out3) {
    if (a == 4) {  // virtual Cb
        float Nx = Xres[0], Ny = Xres[1], Nz = Xres[2];
        float Cax= Xres[3], Cay= Xres[4], Caz= Xres[5];
        float Cx = Xres[6], Cy = Xres[7], Cz = Xres[8];
        float bx = Cax - Nx, by = Cay - Ny, bz = Caz - Nz;
        float cx = Cx - Cax, cy = Cy - Cay, cz = Cz - Caz;
        float ax = by*cz - bz*cy;
        float ay = bz*cx - bx*cz;
        float az = bx*cy - by*cx;
        out3[0] = -0.58273431f*ax + 0.56802827f*bx - 0.54067466f*cx + Cax;
        out3[1] = -0.58273431f*ay + 0.56802827f*by - 0.54067466f*cy + Cay;
        out3[2] = -0.58273431f*az + 0.56802827f*bz - 0.54067466f*cz + Caz;
    } else {
        out3[0] = Xres[a*3+0];
        out3[1] = Xres[a*3+1];
        out3[2] = Xres[a*3+2];
    }
}

// ---------------------------------------------------------------------------
// Consume one chunk: this thread owns 4 features (lt + 32q) and e-pairs
// [EP0, EP0+NEP). One LDS.128 broadcast feeds 16 fma2.
// acc layout: acc[q*4 + ei]
// ---------------------------------------------------------------------------
template<int NEP>
__device__ __forceinline__ void consume_chunk4(
    const float* __restrict__ FaBase, int EP0,
    const float4* __restrict__ Wrow,   // &g_W4[kq0*EFq + lt]
    ull* __restrict__ acc)
{
    #pragma unroll
    for (int p = 0; p < 4; p++) {
        float4 v0 = Wrow[p*EFq +  0];
        float4 v1 = Wrow[p*EFq + 32];
        float4 v2 = Wrow[p*EFq + 64];
        float4 v3 = Wrow[p*EFq + 96];
        ull W00=rep2(v0.x), W01=rep2(v0.y), W02=rep2(v0.z), W03=rep2(v0.w);
        ull W10=rep2(v1.x), W11=rep2(v1.y), W12=rep2(v1.z), W13=rep2(v1.w);
        ull W20=rep2(v2.x), W21=rep2(v2.y), W22=rep2(v2.z), W23=rep2(v2.w);
        ull W30=rep2(v3.x), W31=rep2(v3.y), W32=rep2(v3.z), W33=rep2(v3.w);
        #pragma unroll
        for (int ei = 0; ei < NEP; ei++) {
            const ulonglong2* m =
                (const ulonglong2*)(FaBase + (EP0+ei)*PADF) + 2*p;
            ulonglong2 qa = m[0], qb = m[1];
            ull a0 = fma2(qa.x, W00, acc[ 0+ei]);
            ull a1 = fma2(qa.x, W10, acc[ 4+ei]);
            ull a2 = fma2(qa.x, W20, acc[ 8+ei]);
            ull a3 = fma2(qa.x, W30, acc[12+ei]);
            a0 = fma2(qa.y, W01, a0);
            a1 = fma2(qa.y, W11, a1);
            a2 = fma2(qa.y, W21, a2);
            a3 = fma2(qa.y, W31, a3);
            a0 = fma2(qb.x, W02, a0);
            a1 = fma2(qb.x, W12, a1);
            a2 = fma2(qb.x, W22, a2);
            a3 = fma2(qb.x, W32, a3);
            a0 = fma2(qb.y, W03, a0);
            a1 = fma2(qb.y, W13, a1);
            a2 = fma2(qb.y, W23, a2);
            a3 = fma2(qb.y, W33, a3);
            acc[ 0+ei] = a0;
            acc[ 4+ei] = a1;
            acc[ 8+ei] = a2;
            acc[12+ei] = a3;
        }
    }
}

// ---------------------------------------------------------------------------
// Fused edge kernel: 4 features/thread, e-pairs split across 4 warps.
//   warp w (w=0..2): e-pairs 4w..4w+3 ; warp 3: e-pairs 12..14
//   lane lt: features lt, lt+32, lt+64, lt+96
// ---------------------------------------------------------------------------
__global__ __launch_bounds__(128) void edge_kernel(
    const float* __restrict__ X,
    const float* __restrict__ atom_mask,
    const float* __restrict__ gamma,
    const float* __restrict__ beta,
    float* __restrict__ outE) {

    const int bi = blockIdx.x;
    const int b  = bi / Lq, i = bi % Lq;
    const int tid = threadIdx.x;

    const int wgrp = tid >> 5;
    const int lt   = tid & 31;
    const int myEP0 = wgrp * 4;
    const int myNEP = (wgrp == 3) ? 3 : 4;

    __shared__ __align__(16) float FaU[3840];     // F half-slab / LN acc buffer
    __shared__ __align__(16) float Epos[Kq][NPEq];
    __shared__ float X2n[Kq][Aq][3];
    __shared__ float amn[Kq][Aq];
    __shared__ float X2i[Aq][3];
    __shared__ float ami[Aq];
    __shared__ int   jn[Kq];
    __shared__ float sg[EFq], sb[EFq];
    __shared__ int   alist[Aq];
    __shared__ int   nact;

    if (tid < Kq) jn[tid] = g_Eidx[bi*Kq + tid];
    if (tid < Aq) {
        loadX2(X + bi*Aq*3, tid, X2i[tid]);
        ami[tid] = 1.0f - atom_mask[bi*Aq + tid];
    }
    sg[tid] = gamma[tid];
    sb[tid] = beta[tid];
    __syncthreads();

    for (int t = tid; t < Kq*Aq; t += 128) {
        int e = t / Aq, a = t % Aq;
        int j = jn[e];
        loadX2(X + (b*Lq + j)*Aq*3, a, X2n[e][a]);
        amn[e][a] = 1.0f - atom_mask[(b*Lq + j)*Aq + a];
    }
    for (int t = tid; t < Kq*NPEq; t += 128) {
        int e = t / NPEq, p = t % NPEq;
        float d  = (float)jn[e] - (float)i;
        int   pp = p & 7;
        float fr = expf((float)(2*pp) * -0.57564627324851148f); // -ln(1e4)/16
        float ang = d * fr;
        Epos[e][p] = (p < 8) ? cosf(ang) : sinf(ang);
    }
    if (tid == 0) {
        int c = 0;
        #pragma unroll
        for (int a = 0; a < Aq; a++) if (ami[a] != 0.f) alist[c++] = a;
        nact = c;
    }
    __syncthreads();

    // ---- PE chunk: init acc for my eps x 4 features (one-time, scalar) ----
    ull acc[16];
    {
        float w[4][16];
        #pragma unroll
        for (int kq = 0; kq < 4; kq++) {
            #pragma unroll
            for (int q = 0; q < 4; q++) {
                float4 v = g_W4[kq*EFq + lt + 32*q];
                w[q][4*kq+0]=v.x; w[q][4*kq+1]=v.y; w[q][4*kq+2]=v.z; w[q][4*kq+3]=v.w;
            }
        }
        #pragma unroll
        for (int ei = 0; ei < 4; ei++) {
            #pragma unroll
            for (int q = 0; q < 4; q++) acc[q*4+ei] = 0;
            if (ei < myNEP) {
                float pv[4][2];
                #pragma unroll
                for (int h = 0; h < 2; h++) {
                    const float* vp = Epos[2*(myEP0+ei) + h];
                    #pragma unroll
                    for (int q = 0; q < 4; q++) {
                        float s = 0.f;
                        #pragma unroll
                        for (int k = 0; k < 16; k++) s = fmaf(w[q][k], vp[k], s);
                        pv[q][h] = s;
                    }
                }
                #pragma unroll
                for (int q = 0; q < 4; q++) acc[q*4+ei] = pack2(pv[q][0], pv[q][1]);
            }
        }
    }

    // ---- main flat chunk loop ----
    const int nchunks = nact * Aq;
    for (int ci = 0; ci < nchunks; ci++) {
        const int ai = ci / Aq;
        const int a  = alist[ai];
        const int b2 = ci - ai * Aq;

        if (b2 == 0 || b2 == 7) {
            __syncthreads();          // previous consume of FaU finished
            if (tid < 105) {
                const int ep  = tid / 7;
                const int b2l = tid % 7;
                const int b2g = ((b2 >= 7) ? 7 : 0) + b2l;
                const float xa0 = X2i[a][0], xa1 = X2i[a][1], xa2 = X2i[a][2];
                const int e0 = 2*ep, e1 = e0 + 1;
                const float act0 = amn[e0][b2g];
                const float act1 = amn[e1][b2g];
                float dx = xa0 - X2n[e0][b2g][0];
                float dy = xa1 - X2n[e0][b2g][1];
                float dz = xa2 - X2n[e0][b2g][2];
                const float D0 = sqrtf(dx*dx + dy*dy + dz*dz + 1e-6f);
                dx = xa0 - X2n[e1][b2g][0];
                dy = xa1 - X2n[e1][b2g][1];
                dz = xa2 - X2n[e1][b2g][2];
                const float D1 = sqrtf(dx*dx + dy*dy + dz*dz + 1e-6f);
                float* slot = &FaU[(b2l*15 + ep)*PADF];
                #pragma unroll
                for (int rr = 0; rr < NRBF; rr++) {
                    const int r = (rr + tid) & 15;       // bank rotation
                    const float mu = (float)r * (20.f/15.f);
                    float x0 = (D0 - mu) * 0.8f;
                    float x1 = (D1 - mu) * 0.8f;
                    float v0 = __expf(-x0*x0) * act0;
                    float v1 = __expf(-x1*x1) * act1;
                    *(float2*)(slot + 2*r) = make_float2(v0, v1);
                }
            }
            __syncthreads();
        }

        const int kq0 = 4 + (a*Aq + b2)*4;
        const float4* Wrow = &g_W4[kq0*EFq + lt];

        const int b2l = (b2 >= 7) ? (b2 - 7) : b2;
        const float* FaBase = &FaU[b2l * 15 * PADF];
        if (wgrp == 3) consume_chunk4<3>(FaBase, myEP0, Wrow, acc);
        else           consume_chunk4<4>(FaBase, myEP0, Wrow, acc);
    }

    // ---- dump acc pairs to smem (reusing FaU), then LayerNorm ----
    __syncthreads();
    #pragma unroll
    for (int ei = 0; ei < 4; ei++) {
        if (ei < myNEP) {
            const int ep = myEP0 + ei;
            #pragma unroll
            for (int q = 0; q < 4; q++) {
                float lo, hi;
                unpack2(acc[q*4+ei], lo, hi);
                *(float2*)&FaU[(ep*EFq + lt + 32*q)*2] = make_float2(lo, hi);
            }
        }
    }
    __syncthreads();

    const int wid = tid >> 5, lid = tid & 31;
    float* outRow = outE + (size_t)bi * (Kq*EFq);
    for (int e = wid; e < Kq; e += 4) {
        const int ep = e >> 1, par = e & 1;
        const float* ab = &FaU[ep*EFq*2 + par];
        float v0 = ab[(lid      )*2];
        float v1 = ab[(lid + 32 )*2];
        float v2 = ab[(lid + 64 )*2];
        float v3 = ab[(lid + 96 )*2];
        float s  = (v0 + v1) + (v2 + v3);
        float sq = fmaf(v0,v0, fmaf(v1,v1, fmaf(v2,v2, v3*v3)));
        #pragma unroll
        for (int o = 16; o > 0; o >>= 1) {
            s  += __shfl_xor_sync(0xffffffffu, s,  o);
            sq += __shfl_xor_sync(0xffffffffu, sq, o);
        }
        float mean = s * (1.f/EFq);
        float var  = sq * (1.f/EFq) - mean*mean;
        float rstd = rsqrtf(var + 1e-5f);
        float* o0 = outRow + e*EFq;
        o0[lid     ] = (v0 - mean) * rstd * sg[lid     ] + sb[lid     ];
        o0[lid + 32] = (v1 - mean) * rstd * sg[lid + 32] + sb[lid + 32];
        o0[lid + 64] = (v2 - mean) * rstd * sg[lid + 64] + sb[lid + 64];
        o0[lid + 96] = (v3 - mean) * rstd * sg[lid + 96] + sb[lid + 96];
    }
}

// ---------------------------------------------------------------------------
extern "C" void kernel_launch(void* const* d_in, const int* in_sizes, int n_in,
                              void* d_out, int out_size) {
    const float* X         = (const float*)d_in[0];
    const float* mask      = (const float*)d_in[1];
    const float* atom_mask = (const float*)d_in[4];
    const float* W         = (const float*)d_in[5];
    const float* gamma     = (const float*)d_in[6];
    const float* beta      = (const float*)d_in[7];

    float* outE   = (float*)d_out;
    float* outIdx = (out_size >= NE + NK) ? (outE + NE) : nullptr;

    prep_kernel<<<NPACKBLK + Bq*Lq, 256>>>(W, X, mask, outIdx);
    edge_kernel<<<Bq*Lq, 128>>>(X, atom_mask, gamma, beta, outE);
}